// round 12
// baseline (speedup 1.0000x reference)
#include <cuda_runtime.h>
#include <cstddef>

#define NATOMS 512
#define DDIM   128
#define KDIM   1536   // 3*N
#define NSTR   6
#define NSPEC  4
#define TILE   4      // atoms per MLP block
#define XS     132    // activation smem row stride (floats)
#define WS     132    // weight smem row stride (floats), 16B-aligned rows
#define WS64   66     // in u64 units
#define NTILES_MAX (NATOMS / TILE + NSPEC - 1)   // 131
#define MLP_THREADS 512
#define FXSCALE 4294967296.0          // 2^32
#define FXINV   (1.0 / 4294967296.0)

typedef unsigned long long u64;

#define FMA_F32X2(d, a, b, c) \
    asm("fma.rn.f32x2 %0, %1, %2, %3;" : "=l"(d) : "l"(a), "l"(b), "l"(c))
#define PACK2_F32X2(out, v) \
    asm("mov.b64 %0, {%1, %1};" : "=l"(out) : "r"(__float_as_uint(v)))

__device__ __forceinline__ float f32x2_lo(u64 v) { return __uint_as_float((unsigned)(v & 0xFFFFFFFFu)); }
__device__ __forceinline__ float f32x2_hi(u64 v) { return __uint_as_float((unsigned)(v >> 32)); }
__device__ __forceinline__ float f32x2_sum(u64 v) { return f32x2_lo(v) + f32x2_hi(v); }

// Scratch (BSS zero-initialized at module load; finalize re-zeroes each call)
__device__ u64   g_facc[KDIM];                                  // fixed-point force accum
__device__ __align__(16) float g_separt[(NSTR + 1) * NATOMS];   // stress + energy partials
__device__ __align__(16) float g_G[NATOMS * DDIM];              // per-atom dE/ddesc
__device__ int   g_flag[NATOMS];                                // per-atom G-ready flags
__device__ float g_dummy;                                       // keep-alive sink (never read)

// ---------------------------------------------------------------------------
// Kernel 1: species-batched MLP fwd+bwd + PDL trigger + per-atom flag release.
// ---------------------------------------------------------------------------
__global__ __launch_bounds__(MLP_THREADS) void nnp_mlp_kernel(
    const float* __restrict__ desc,   // [N, D]
    const float* __restrict__ SG,     // [N, 6, D]
    const float* __restrict__ W0,     // [S, H, D]
    const float* __restrict__ b0,     // [S, H]
    const float* __restrict__ W1,     // [S, H, H]
    const float* __restrict__ b1,     // [S, H]
    const float* __restrict__ W2,     // [S, 1, H]
    const float* __restrict__ b2,     // [S, 1]
    const int*   __restrict__ species)
{
    asm volatile("griddepcontrol.launch_dependents;");

    const int tid  = threadIdx.x;
    const int ty   = tid >> 2;     // fwd: row 0..127
    const int tx   = tid & 3;      // fwd: atom
    const int wid  = tid >> 5;
    const int lane = tid & 31;
    const int h   = tid >> 8;           // bwd: jj half
    const int r2  = (tid >> 2) & 63;    // bwd: row pair
    const int ax  = tid & 3;            // bwd: atom

    extern __shared__ float sm[];
    float* W0s = sm;
    float* W1s = sm + DDIM * WS;
    float* X   = sm + 2 * DDIM * WS;
    float* H0  = X  + TILE * XS;
    float* A0  = H0 + TILE * XS;
    float* D1  = A0 + TILE * XS;
    float* Ep  = D1 + TILE * XS;
    float* Pb  = Ep + MLP_THREADS;
    __shared__ int sSpec[NATOMS];
    __shared__ int idx[TILE];
    __shared__ int sh_cnt[NSPEC];
    __shared__ int sh_s, sh_j, sh_m;

    sSpec[tid] = species[tid];
    __syncthreads();

    if (wid == 0) {
        int c0 = 0, c1 = 0, c2 = 0, c3 = 0;
        #pragma unroll
        for (int c = 0; c < NATOMS; c += 32) {
            const int spv = sSpec[c + lane];
            c0 += __popc(__ballot_sync(0xFFFFFFFFu, spv == 0));
            c1 += __popc(__ballot_sync(0xFFFFFFFFu, spv == 1));
            c2 += __popc(__ballot_sync(0xFFFFFFFFu, spv == 2));
            c3 += __popc(__ballot_sync(0xFFFFFFFFu, spv == 3));
        }
        if (lane == 0) { sh_cnt[0] = c0; sh_cnt[1] = c1; sh_cnt[2] = c2; sh_cnt[3] = c3; }
    }
    __syncthreads();

    if (tid == 0) {
        int b = blockIdx.x, sp = 0, acc = 0;
        for (; sp < NSPEC; sp++) {
            const int t = (sh_cnt[sp] + TILE - 1) / TILE;
            if (b < acc + t) break;
            acc += t;
        }
        sh_s = sp;
        if (sp < NSPEC) {
            const int jj = b - acc;
            sh_j = jj;
            const int mm = sh_cnt[sp] - jj * TILE;
            sh_m = mm > TILE ? TILE : mm;
        }
    }
    __syncthreads();
    const int s = sh_s;
    if (s >= NSPEC) return;
    const int j = sh_j;
    const int m = sh_m;

    const float pb0 = b0[s * DDIM + ty];
    const float pb1 = b1[s * DDIM + ty];
    const float pw2 = W2[s * DDIM + ty];
    const float pb2 = b2[s];

    if (wid == 0) {
        int base = 0;
        #pragma unroll
        for (int c = 0; c < NATOMS; c += 32) {
            const int spv = sSpec[c + lane];
            const unsigned mask = __ballot_sync(0xFFFFFFFFu, spv == s);
            if (spv == s) {
                const int rank = base + __popc(mask & ((1u << lane) - 1u));
                const int rel = rank - j * TILE;
                if (rel >= 0 && rel < TILE) idx[rel] = c + lane;
            }
            base += __popc(mask);
        }
    }
    __syncthreads();

    float4 sv[2]; int srs[2], sn[2], sa[2]; bool svd[2];
    #pragma unroll
    for (int q = 0; q < 2; q++) {
        const int t = wid + q * 16;
        svd[q] = t < NSTR * m;
        srs[q] = 0; sn[q] = 0; sa[q] = 0;
        if (svd[q]) {
            sa[q] = t / NSTR; srs[q] = t % NSTR; sn[q] = idx[sa[q]];
            sv[q] = ((const float4*)(SG + ((size_t)sn[q] * NSTR + srs[q]) * DDIM))[lane];
        }
    }

    {
        const int a = tid >> 7, d = tid & 127;
        X[a * XS + d] = (a < m) ? desc[(size_t)idx[a] * DDIM + d] : 0.f;
    }
    {
        const float4* w0g = (const float4*)(W0 + (size_t)s * DDIM * DDIM);
        const float4* w1g = (const float4*)(W1 + (size_t)s * DDIM * DDIM);
        #pragma unroll 8
        for (int f = tid; f < DDIM * 32; f += MLP_THREADS) {
            const int r = f >> 5, d4 = f & 31;
            *(float4*)(W0s + r * WS + d4 * 4) = w0g[f];
            *(float4*)(W1s + r * WS + d4 * 4) = w1g[f];
        }
    }
    __syncthreads();

    // ---- forward layer 0 ----
    {
        u64 a0 = 0ull, a1 = 0ull, a2 = 0ull, a3 = 0ull;
        const ulonglong2* Xd = (const ulonglong2*)(X + tx * XS);
        const ulonglong2* Wd = (const ulonglong2*)(W0s + (size_t)ty * WS);
        #pragma unroll
        for (int dq = 0; dq < 32; dq += 2) {
            ulonglong2 w0v = Wd[dq],     x0v = Xd[dq];
            ulonglong2 w1v = Wd[dq + 1], x1v = Xd[dq + 1];
            FMA_F32X2(a0, w0v.x, x0v.x, a0);
            FMA_F32X2(a1, w0v.y, x0v.y, a1);
            FMA_F32X2(a2, w1v.x, x1v.x, a2);
            FMA_F32X2(a3, w1v.y, x1v.y, a3);
        }
        const float hv = tanhf((f32x2_sum(a0) + f32x2_sum(a1))
                             + (f32x2_sum(a2) + f32x2_sum(a3)) + pb0);
        H0[tx * XS + ty] = hv;
        A0[tx * XS + ty] = 1.f - hv * hv;
    }
    __syncthreads();

    // ---- forward layer 1 + output partials ----
    {
        u64 a0 = 0ull, a1 = 0ull, a2 = 0ull, a3 = 0ull;
        const ulonglong2* Xd = (const ulonglong2*)(H0 + tx * XS);
        const ulonglong2* Wd = (const ulonglong2*)(W1s + (size_t)ty * WS);
        #pragma unroll
        for (int dq = 0; dq < 32; dq += 2) {
            ulonglong2 w0v = Wd[dq],     x0v = Xd[dq];
            ulonglong2 w1v = Wd[dq + 1], x1v = Xd[dq + 1];
            FMA_F32X2(a0, w0v.x, x0v.x, a0);
            FMA_F32X2(a1, w0v.y, x0v.y, a1);
            FMA_F32X2(a2, w1v.x, x1v.x, a2);
            FMA_F32X2(a3, w1v.y, x1v.y, a3);
        }
        const float hv = tanhf((f32x2_sum(a0) + f32x2_sum(a1))
                             + (f32x2_sum(a2) + f32x2_sum(a3)) + pb1);
        Ep[tid] = pw2 * hv;
        D1[tx * XS + ty] = pw2 * (1.f - hv * hv);
    }
    __syncthreads();

    if (tid < m) {
        float e0 = pb2, e1 = 0.f, e2 = 0.f, e3 = 0.f;
        #pragma unroll 8
        for (int t2 = 0; t2 < 128; t2 += 4) {
            e0 += Ep[(t2 + 0) * 4 + tid];
            e1 += Ep[(t2 + 1) * 4 + tid];
            e2 += Ep[(t2 + 2) * 4 + tid];
            e3 += Ep[(t2 + 3) * 4 + tid];
        }
        g_separt[NSTR * NATOMS + idx[tid]] = (e0 + e1) + (e2 + e3);
    }

    // ---- backward B1: D0 = (W1^T @ D1) * A0, split-K ----
    u64 bacc0, bacc1;
    {
        u64 acc0 = 0ull, acc1 = 0ull;
        const int jbase = h * 64;
        const float4* Dp = (const float4*)(D1 + ax * XS + jbase);
        const u64* Wb = (const u64*)W1s;
        #pragma unroll
        for (int jq = 0; jq < 16; jq++) {
            const float4 dv = Dp[jq];
            u64 da, db, dc, dd;
            PACK2_F32X2(da, dv.x); PACK2_F32X2(db, dv.y);
            PACK2_F32X2(dc, dv.z); PACK2_F32X2(dd, dv.w);
            const size_t wb = (size_t)(jbase + jq * 4) * WS64 + r2;
            FMA_F32X2(acc0, Wb[wb + 0 * WS64], da, acc0);
            FMA_F32X2(acc1, Wb[wb + 1 * WS64], db, acc1);
            FMA_F32X2(acc0, Wb[wb + 2 * WS64], dc, acc0);
            FMA_F32X2(acc1, Wb[wb + 3 * WS64], dd, acc1);
        }
        bacc0 = acc0; bacc1 = acc1;
    }
    if (h == 1) {
        Pb[ax * DDIM + r2 * 2 + 0] = f32x2_lo(bacc0) + f32x2_lo(bacc1);
        Pb[ax * DDIM + r2 * 2 + 1] = f32x2_hi(bacc0) + f32x2_hi(bacc1);
    }
    __syncthreads();
    if (h == 0) {
        A0[ax * XS + r2 * 2 + 0] *= f32x2_lo(bacc0) + f32x2_lo(bacc1) + Pb[ax * DDIM + r2 * 2 + 0];
        A0[ax * XS + r2 * 2 + 1] *= f32x2_hi(bacc0) + f32x2_hi(bacc1) + Pb[ax * DDIM + r2 * 2 + 1];
    }
    __syncthreads();

    // ---- backward B2: G = W0^T @ D0, split-K ----
    {
        u64 acc0 = 0ull, acc1 = 0ull;
        const int jbase = h * 64;
        const float4* Dp = (const float4*)(A0 + ax * XS + jbase);
        const u64* Wb = (const u64*)W0s;
        #pragma unroll
        for (int jq = 0; jq < 16; jq++) {
            const float4 dv = Dp[jq];
            u64 da, db, dc, dd;
            PACK2_F32X2(da, dv.x); PACK2_F32X2(db, dv.y);
            PACK2_F32X2(dc, dv.z); PACK2_F32X2(dd, dv.w);
            const size_t wb = (size_t)(jbase + jq * 4) * WS64 + r2;
            FMA_F32X2(acc0, Wb[wb + 0 * WS64], da, acc0);
            FMA_F32X2(acc1, Wb[wb + 1 * WS64], db, acc1);
            FMA_F32X2(acc0, Wb[wb + 2 * WS64], dc, acc0);
            FMA_F32X2(acc1, Wb[wb + 3 * WS64], dd, acc1);
        }
        bacc0 = acc0; bacc1 = acc1;
    }
    if (h == 1) {
        Pb[ax * DDIM + r2 * 2 + 0] = f32x2_lo(bacc0) + f32x2_lo(bacc1);
        Pb[ax * DDIM + r2 * 2 + 1] = f32x2_hi(bacc0) + f32x2_hi(bacc1);
    }
    __syncthreads();
    if (h == 0) {
        const float g0 = f32x2_lo(bacc0) + f32x2_lo(bacc1) + Pb[ax * DDIM + r2 * 2 + 0];
        const float g1 = f32x2_hi(bacc0) + f32x2_hi(bacc1) + Pb[ax * DDIM + r2 * 2 + 1];
        H0[ax * XS + r2 * 2 + 0] = g0;
        H0[ax * XS + r2 * 2 + 1] = g1;
        if (ax < m)
            *(float2*)(g_G + (size_t)idx[ax] * DDIM + r2 * 2) = make_float2(g0, g1);
    }
    __syncthreads();

    if (tid < m) {
        __threadfence();
        ((volatile int*)g_flag)[idx[tid]] = 1;
    }

    #pragma unroll
    for (int q = 0; q < 2; q++) {
        if (svd[q]) {
            const float4 g = ((const float4*)(H0 + sa[q] * XS))[lane];
            float svv = sv[q].x * g.x + sv[q].y * g.y + sv[q].z * g.z + sv[q].w * g.w;
            #pragma unroll
            for (int off = 16; off > 0; off >>= 1)
                svv += __shfl_xor_sync(0xFFFFFFFFu, svv, off);
            if (lane == 0) g_separt[(size_t)srs[q] * NATOMS + sn[q]] = svv;
        }
    }
}

// ---------------------------------------------------------------------------
// Kernel 2: stream coord_grads. PDL secondary of MLP; PDL primary of finalize.
// If G not ready: prefetch own 128KB slab into L2, then spin. Force partials
// accumulate via deterministic fixed-point integer atomics.
// ---------------------------------------------------------------------------
__global__ __launch_bounds__(256) void nnp_stream_kernel(
    const float* __restrict__ CG)     // [N, KDIM, D]
{
    asm volatile("griddepcontrol.launch_dependents;");

    const int b    = blockIdx.x;
    const int n    = b / 6;
    const int chnk = b % 6;
    const int wid  = threadIdx.x >> 5;
    const int lane = threadIdx.x & 31;

    const int k0 = chnk * 256 + wid * 32;
    const float4* base = reinterpret_cast<const float4*>(
        CG + ((size_t)n * KDIM + k0) * DDIM);

    __shared__ int s_ready;
    if (threadIdx.x == 0) s_ready = ((volatile int*)g_flag)[n];
    __syncthreads();

    if (!s_ready) {
        const float4* pf = reinterpret_cast<const float4*>(
            CG + ((size_t)n * KDIM + chnk * 256) * DDIM) + threadIdx.x;
        float ax = 0.f, ay = 0.f, az = 0.f, aw = 0.f;
        #pragma unroll 8
        for (int i = 0; i < 32; i++) {
            float4 v = __ldcg(pf + i * 256);
            ax += v.x; ay += v.y; az += v.z; aw += v.w;
        }
        if (__float_as_uint((ax + ay) + (az + aw)) == 0xDEADBEEFu)
            g_dummy = ax;
        if (threadIdx.x == 0) {
            while (((volatile int*)g_flag)[n] == 0) __nanosleep(128);
            __threadfence();
        }
    }
    __syncthreads();

    const float4 gv = reinterpret_cast<const float4*>(g_G + (size_t)n * DDIM)[lane];

    #pragma unroll
    for (int it = 0; it < 8; it++) {
        const float4* p = base + (size_t)(it * 4) * 32 + lane;
        float4 v0 = __ldcs(p + 0 * 32);
        float4 v1 = __ldcs(p + 1 * 32);
        float4 v2 = __ldcs(p + 2 * 32);
        float4 v3 = __ldcs(p + 3 * 32);
        float s0 = v0.x * gv.x + v0.y * gv.y + v0.z * gv.z + v0.w * gv.w;
        float s1 = v1.x * gv.x + v1.y * gv.y + v1.z * gv.z + v1.w * gv.w;
        float s2 = v2.x * gv.x + v2.y * gv.y + v2.z * gv.z + v2.w * gv.w;
        float s3 = v3.x * gv.x + v3.y * gv.y + v3.z * gv.z + v3.w * gv.w;
        #pragma unroll
        for (int off = 16; off > 0; off >>= 1) {
            s0 += __shfl_xor_sync(0xFFFFFFFFu, s0, off);
            s1 += __shfl_xor_sync(0xFFFFFFFFu, s1, off);
            s2 += __shfl_xor_sync(0xFFFFFFFFu, s2, off);
            s3 += __shfl_xor_sync(0xFFFFFFFFu, s3, off);
        }
        if (lane == 0) {
            atomicAdd(&g_facc[k0 + it * 4 + 0],
                      (u64)(long long)__double2ll_rn((double)s0 * FXSCALE));
            atomicAdd(&g_facc[k0 + it * 4 + 1],
                      (u64)(long long)__double2ll_rn((double)s1 * FXSCALE));
            atomicAdd(&g_facc[k0 + it * 4 + 2],
                      (u64)(long long)__double2ll_rn((double)s2 * FXSCALE));
            atomicAdd(&g_facc[k0 + it * 4 + 3],
                      (u64)(long long)__double2ll_rn((double)s3 * FXSCALE));
        }
    }
}

// ---------------------------------------------------------------------------
// Kernel 3: finalize (PDL secondary of stream). Converts fixed-point forces,
// reduces stress/energy, resets accumulators + flags for next graph replay.
// ---------------------------------------------------------------------------
__global__ __launch_bounds__(256) void nnp_finalize_kernel(
    float* __restrict__ out, const float* __restrict__ volume)
{
    asm volatile("griddepcontrol.wait;");   // all stream atomics visible

    const int tid = threadIdx.x;
    const int k = blockIdx.x * 256 + tid;
    if (k < KDIM) {
        const long long v = (long long)g_facc[k];
        out[1 + k] = (float)((double)v * FXINV);
        g_facc[k] = 0ull;
    }
    if (blockIdx.x == 6) {
        const int w    = tid >> 5;
        const int lane = tid & 31;
        if (w < NSTR + 1) {
            const float4* basep = (const float4*)(g_separt + (size_t)w * NATOMS);
            float4 v0 = basep[lane + 0 * 32];
            float4 v1 = basep[lane + 1 * 32];
            float4 v2 = basep[lane + 2 * 32];
            float4 v3 = basep[lane + 3 * 32];
            float s = (v0.x + v0.y + v0.z + v0.w) + (v1.x + v1.y + v1.z + v1.w)
                    + (v2.x + v2.y + v2.z + v2.w) + (v3.x + v3.y + v3.z + v3.w);
            #pragma unroll
            for (int off = 16; off > 0; off >>= 1)
                s += __shfl_xor_sync(0xFFFFFFFFu, s, off);
            if (lane == 0) {
                if (w < NSTR) out[1 + KDIM + w] = -s / volume[0];
                else          out[0] = s;
            }
        }
        g_flag[tid]       = 0;
        g_flag[tid + 256] = 0;
    }
}

extern "C" void kernel_launch(void* const* d_in, const int* in_sizes, int n_in,
                              void* d_out, int out_size)
{
    const float* desc    = (const float*)d_in[0];
    const float* CG      = (const float*)d_in[1];
    const float* SG      = (const float*)d_in[2];
    const float* W0      = (const float*)d_in[3];
    const float* b0      = (const float*)d_in[4];
    const float* W1      = (const float*)d_in[5];
    const float* b1      = (const float*)d_in[6];
    const float* W2      = (const float*)d_in[7];
    const float* b2      = (const float*)d_in[8];
    const float* volume  = (const float*)d_in[9];
    const int*   species = (const int*)  d_in[10];
    float* out = (float*)d_out;

    const int mlp_smem = (2 * DDIM * WS + 4 * TILE * XS + 2 * MLP_THREADS) * sizeof(float);
    cudaFuncSetAttribute(nnp_mlp_kernel,
                         cudaFuncAttributeMaxDynamicSharedMemorySize, mlp_smem);

    nnp_mlp_kernel<<<NTILES_MAX, MLP_THREADS, mlp_smem>>>(
        desc, SG, W0, b0, W1, b1, W2, b2, species);

    cudaLaunchAttribute pdl[1];
    pdl[0].id = cudaLaunchAttributeProgrammaticStreamSerialization;
    pdl[0].val.programmaticStreamSerializationAllowed = 1;

    cudaLaunchConfig_t cfg = {};
    cfg.gridDim  = dim3(NATOMS * 6);
    cfg.blockDim = dim3(256);
    cfg.dynamicSmemBytes = 0;
    cfg.stream = 0;
    cfg.attrs = pdl;
    cfg.numAttrs = 1;
    cudaLaunchKernelEx(&cfg, nnp_stream_kernel, CG);

    cudaLaunchConfig_t cfg2 = {};
    cfg2.gridDim  = dim3(7);
    cfg2.blockDim = dim3(256);
    cfg2.dynamicSmemBytes = 0;
    cfg2.stream = 0;
    cfg2.attrs = pdl;
    cfg2.numAttrs = 1;
    cudaLaunchKernelEx(&cfg2, nnp_finalize_kernel, out, volume);
}

// round 13
// speedup vs baseline: 2.3652x; 2.3652x over previous
#include <cuda_runtime.h>
#include <cstddef>

#define NATOMS 512
#define DDIM   128
#define KDIM   1536   // 3*N
#define NSTR   6
#define KTOT   (KDIM + NSTR + 1)
#define NSPEC  4
#define TILE   4      // atoms per MLP block
#define XS     132    // activation smem row stride (floats)
#define WS     132    // weight smem row stride (floats), 16B-aligned rows
#define WS64   66     // in u64 units
#define NTILES_MAX (NATOMS / TILE + NSPEC - 1)   // 131
#define MLP_THREADS 512

typedef unsigned long long u64;

#define FMA_F32X2(d, a, b, c) \
    asm("fma.rn.f32x2 %0, %1, %2, %3;" : "=l"(d) : "l"(a), "l"(b), "l"(c))
#define PACK2_F32X2(out, v) \
    asm("mov.b64 %0, {%1, %1};" : "=l"(out) : "r"(__float_as_uint(v)))

__device__ __forceinline__ float f32x2_lo(u64 v) { return __uint_as_float((unsigned)(v & 0xFFFFFFFFu)); }
__device__ __forceinline__ float f32x2_hi(u64 v) { return __uint_as_float((unsigned)(v >> 32)); }
__device__ __forceinline__ float f32x2_sum(u64 v) { return f32x2_lo(v) + f32x2_hi(v); }

// Scratch
__device__ __align__(16) float g_partial[KDIM * NATOMS];        // force partials (3 MB)
__device__ __align__(16) float g_separt[(NSTR + 1) * NATOMS];   // stress + energy partials
__device__ __align__(16) float g_G[NATOMS * DDIM];              // per-atom dE/ddesc
__device__ int   g_flag[NATOMS];                                // per-atom G-ready flags
__device__ float g_dummy;                                       // keep-alive sink (never read)

// ---------------------------------------------------------------------------
// Kernel 1: species-batched MLP fwd+bwd + PDL trigger + per-atom flag release.
// ---------------------------------------------------------------------------
__global__ __launch_bounds__(MLP_THREADS) void nnp_mlp_kernel(
    const float* __restrict__ desc,   // [N, D]
    const float* __restrict__ SG,     // [N, 6, D]
    const float* __restrict__ W0,     // [S, H, D]
    const float* __restrict__ b0,     // [S, H]
    const float* __restrict__ W1,     // [S, H, H]
    const float* __restrict__ b1,     // [S, H]
    const float* __restrict__ W2,     // [S, 1, H]
    const float* __restrict__ b2,     // [S, 1]
    const int*   __restrict__ species)
{
    asm volatile("griddepcontrol.launch_dependents;");

    const int tid  = threadIdx.x;
    const int ty   = tid >> 2;     // fwd: row 0..127
    const int tx   = tid & 3;      // fwd: atom
    const int wid  = tid >> 5;
    const int lane = tid & 31;
    const int h   = tid >> 8;           // bwd: jj half
    const int r2  = (tid >> 2) & 63;    // bwd: row pair
    const int ax  = tid & 3;            // bwd: atom

    extern __shared__ float sm[];
    float* W0s = sm;
    float* W1s = sm + DDIM * WS;
    float* X   = sm + 2 * DDIM * WS;
    float* H0  = X  + TILE * XS;
    float* A0  = H0 + TILE * XS;
    float* D1  = A0 + TILE * XS;
    float* Ep  = D1 + TILE * XS;
    float* Pb  = Ep + MLP_THREADS;
    __shared__ int sSpec[NATOMS];
    __shared__ int idx[TILE];
    __shared__ int sh_cnt[NSPEC];
    __shared__ int sh_s, sh_j, sh_m;

    sSpec[tid] = species[tid];
    __syncthreads();

    if (wid == 0) {
        int c0 = 0, c1 = 0, c2 = 0, c3 = 0;
        #pragma unroll
        for (int c = 0; c < NATOMS; c += 32) {
            const int spv = sSpec[c + lane];
            c0 += __popc(__ballot_sync(0xFFFFFFFFu, spv == 0));
            c1 += __popc(__ballot_sync(0xFFFFFFFFu, spv == 1));
            c2 += __popc(__ballot_sync(0xFFFFFFFFu, spv == 2));
            c3 += __popc(__ballot_sync(0xFFFFFFFFu, spv == 3));
        }
        if (lane == 0) { sh_cnt[0] = c0; sh_cnt[1] = c1; sh_cnt[2] = c2; sh_cnt[3] = c3; }
    }
    __syncthreads();

    if (tid == 0) {
        int b = blockIdx.x, sp = 0, acc = 0;
        for (; sp < NSPEC; sp++) {
            const int t = (sh_cnt[sp] + TILE - 1) / TILE;
            if (b < acc + t) break;
            acc += t;
        }
        sh_s = sp;
        if (sp < NSPEC) {
            const int jj = b - acc;
            sh_j = jj;
            const int mm = sh_cnt[sp] - jj * TILE;
            sh_m = mm > TILE ? TILE : mm;
        }
    }
    __syncthreads();
    const int s = sh_s;
    if (s >= NSPEC) return;
    const int j = sh_j;
    const int m = sh_m;

    const float pb0 = b0[s * DDIM + ty];
    const float pb1 = b1[s * DDIM + ty];
    const float pw2 = W2[s * DDIM + ty];
    const float pb2 = b2[s];

    if (wid == 0) {
        int base = 0;
        #pragma unroll
        for (int c = 0; c < NATOMS; c += 32) {
            const int spv = sSpec[c + lane];
            const unsigned mask = __ballot_sync(0xFFFFFFFFu, spv == s);
            if (spv == s) {
                const int rank = base + __popc(mask & ((1u << lane) - 1u));
                const int rel = rank - j * TILE;
                if (rel >= 0 && rel < TILE) idx[rel] = c + lane;
            }
            base += __popc(mask);
        }
    }
    __syncthreads();

    float4 sv[2]; int srs[2], sn[2], sa[2]; bool svd[2];
    #pragma unroll
    for (int q = 0; q < 2; q++) {
        const int t = wid + q * 16;
        svd[q] = t < NSTR * m;
        srs[q] = 0; sn[q] = 0; sa[q] = 0;
        if (svd[q]) {
            sa[q] = t / NSTR; srs[q] = t % NSTR; sn[q] = idx[sa[q]];
            sv[q] = ((const float4*)(SG + ((size_t)sn[q] * NSTR + srs[q]) * DDIM))[lane];
        }
    }

    {
        const int a = tid >> 7, d = tid & 127;
        X[a * XS + d] = (a < m) ? desc[(size_t)idx[a] * DDIM + d] : 0.f;
    }
    {
        const float4* w0g = (const float4*)(W0 + (size_t)s * DDIM * DDIM);
        const float4* w1g = (const float4*)(W1 + (size_t)s * DDIM * DDIM);
        #pragma unroll 8
        for (int f = tid; f < DDIM * 32; f += MLP_THREADS) {
            const int r = f >> 5, d4 = f & 31;
            *(float4*)(W0s + r * WS + d4 * 4) = w0g[f];
            *(float4*)(W1s + r * WS + d4 * 4) = w1g[f];
        }
    }
    __syncthreads();

    // ---- forward layer 0 ----
    {
        u64 a0 = 0ull, a1 = 0ull, a2 = 0ull, a3 = 0ull;
        const ulonglong2* Xd = (const ulonglong2*)(X + tx * XS);
        const ulonglong2* Wd = (const ulonglong2*)(W0s + (size_t)ty * WS);
        #pragma unroll
        for (int dq = 0; dq < 32; dq += 2) {
            ulonglong2 w0v = Wd[dq],     x0v = Xd[dq];
            ulonglong2 w1v = Wd[dq + 1], x1v = Xd[dq + 1];
            FMA_F32X2(a0, w0v.x, x0v.x, a0);
            FMA_F32X2(a1, w0v.y, x0v.y, a1);
            FMA_F32X2(a2, w1v.x, x1v.x, a2);
            FMA_F32X2(a3, w1v.y, x1v.y, a3);
        }
        const float hv = tanhf((f32x2_sum(a0) + f32x2_sum(a1))
                             + (f32x2_sum(a2) + f32x2_sum(a3)) + pb0);
        H0[tx * XS + ty] = hv;
        A0[tx * XS + ty] = 1.f - hv * hv;
    }
    __syncthreads();

    // ---- forward layer 1 + output partials ----
    {
        u64 a0 = 0ull, a1 = 0ull, a2 = 0ull, a3 = 0ull;
        const ulonglong2* Xd = (const ulonglong2*)(H0 + tx * XS);
        const ulonglong2* Wd = (const ulonglong2*)(W1s + (size_t)ty * WS);
        #pragma unroll
        for (int dq = 0; dq < 32; dq += 2) {
            ulonglong2 w0v = Wd[dq],     x0v = Xd[dq];
            ulonglong2 w1v = Wd[dq + 1], x1v = Xd[dq + 1];
            FMA_F32X2(a0, w0v.x, x0v.x, a0);
            FMA_F32X2(a1, w0v.y, x0v.y, a1);
            FMA_F32X2(a2, w1v.x, x1v.x, a2);
            FMA_F32X2(a3, w1v.y, x1v.y, a3);
        }
        const float hv = tanhf((f32x2_sum(a0) + f32x2_sum(a1))
                             + (f32x2_sum(a2) + f32x2_sum(a3)) + pb1);
        Ep[tid] = pw2 * hv;
        D1[tx * XS + ty] = pw2 * (1.f - hv * hv);
    }
    __syncthreads();

    if (tid < m) {
        float e0 = pb2, e1 = 0.f, e2 = 0.f, e3 = 0.f;
        #pragma unroll 8
        for (int t2 = 0; t2 < 128; t2 += 4) {
            e0 += Ep[(t2 + 0) * 4 + tid];
            e1 += Ep[(t2 + 1) * 4 + tid];
            e2 += Ep[(t2 + 2) * 4 + tid];
            e3 += Ep[(t2 + 3) * 4 + tid];
        }
        g_separt[NSTR * NATOMS + idx[tid]] = (e0 + e1) + (e2 + e3);
    }

    // ---- backward B1: D0 = (W1^T @ D1) * A0, split-K ----
    u64 bacc0, bacc1;
    {
        u64 acc0 = 0ull, acc1 = 0ull;
        const int jbase = h * 64;
        const float4* Dp = (const float4*)(D1 + ax * XS + jbase);
        const u64* Wb = (const u64*)W1s;
        #pragma unroll
        for (int jq = 0; jq < 16; jq++) {
            const float4 dv = Dp[jq];
            u64 da, db, dc, dd;
            PACK2_F32X2(da, dv.x); PACK2_F32X2(db, dv.y);
            PACK2_F32X2(dc, dv.z); PACK2_F32X2(dd, dv.w);
            const size_t wb = (size_t)(jbase + jq * 4) * WS64 + r2;
            FMA_F32X2(acc0, Wb[wb + 0 * WS64], da, acc0);
            FMA_F32X2(acc1, Wb[wb + 1 * WS64], db, acc1);
            FMA_F32X2(acc0, Wb[wb + 2 * WS64], dc, acc0);
            FMA_F32X2(acc1, Wb[wb + 3 * WS64], dd, acc1);
        }
        bacc0 = acc0; bacc1 = acc1;
    }
    if (h == 1) {
        Pb[ax * DDIM + r2 * 2 + 0] = f32x2_lo(bacc0) + f32x2_lo(bacc1);
        Pb[ax * DDIM + r2 * 2 + 1] = f32x2_hi(bacc0) + f32x2_hi(bacc1);
    }
    __syncthreads();
    if (h == 0) {
        A0[ax * XS + r2 * 2 + 0] *= f32x2_lo(bacc0) + f32x2_lo(bacc1) + Pb[ax * DDIM + r2 * 2 + 0];
        A0[ax * XS + r2 * 2 + 1] *= f32x2_hi(bacc0) + f32x2_hi(bacc1) + Pb[ax * DDIM + r2 * 2 + 1];
    }
    __syncthreads();

    // ---- backward B2: G = W0^T @ D0, split-K ----
    {
        u64 acc0 = 0ull, acc1 = 0ull;
        const int jbase = h * 64;
        const float4* Dp = (const float4*)(A0 + ax * XS + jbase);
        const u64* Wb = (const u64*)W0s;
        #pragma unroll
        for (int jq = 0; jq < 16; jq++) {
            const float4 dv = Dp[jq];
            u64 da, db, dc, dd;
            PACK2_F32X2(da, dv.x); PACK2_F32X2(db, dv.y);
            PACK2_F32X2(dc, dv.z); PACK2_F32X2(dd, dv.w);
            const size_t wb = (size_t)(jbase + jq * 4) * WS64 + r2;
            FMA_F32X2(acc0, Wb[wb + 0 * WS64], da, acc0);
            FMA_F32X2(acc1, Wb[wb + 1 * WS64], db, acc1);
            FMA_F32X2(acc0, Wb[wb + 2 * WS64], dc, acc0);
            FMA_F32X2(acc1, Wb[wb + 3 * WS64], dd, acc1);
        }
        bacc0 = acc0; bacc1 = acc1;
    }
    if (h == 1) {
        Pb[ax * DDIM + r2 * 2 + 0] = f32x2_lo(bacc0) + f32x2_lo(bacc1);
        Pb[ax * DDIM + r2 * 2 + 1] = f32x2_hi(bacc0) + f32x2_hi(bacc1);
    }
    __syncthreads();
    if (h == 0) {
        const float g0 = f32x2_lo(bacc0) + f32x2_lo(bacc1) + Pb[ax * DDIM + r2 * 2 + 0];
        const float g1 = f32x2_hi(bacc0) + f32x2_hi(bacc1) + Pb[ax * DDIM + r2 * 2 + 1];
        H0[ax * XS + r2 * 2 + 0] = g0;
        H0[ax * XS + r2 * 2 + 1] = g1;
        if (ax < m)
            *(float2*)(g_G + (size_t)idx[ax] * DDIM + r2 * 2) = make_float2(g0, g1);
    }
    __syncthreads();

    // ---- release per-atom flags (G complete + visible) ----
    if (tid < m) {
        __threadfence();
        ((volatile int*)g_flag)[idx[tid]] = 1;
    }

    // ---- stress partials ----
    #pragma unroll
    for (int q = 0; q < 2; q++) {
        if (svd[q]) {
            const float4 g = ((const float4*)(H0 + sa[q] * XS))[lane];
            float svv = sv[q].x * g.x + sv[q].y * g.y + sv[q].z * g.z + sv[q].w * g.w;
            #pragma unroll
            for (int off = 16; off > 0; off >>= 1)
                svv += __shfl_xor_sync(0xFFFFFFFFu, svv, off);
            if (lane == 0) g_separt[(size_t)srs[q] * NATOMS + sn[q]] = svv;
        }
    }
}

// ---------------------------------------------------------------------------
// Kernel 2: stream coord_grads. PDL secondary of MLP; PDL primary of reduce.
// If G not ready: prefetch own 128KB slab into L2 (useful DRAM work), spin.
// ---------------------------------------------------------------------------
__global__ __launch_bounds__(256) void nnp_stream_kernel(
    const float* __restrict__ CG)     // [N, KDIM, D]
{
    asm volatile("griddepcontrol.launch_dependents;");

    const int b    = blockIdx.x;
    const int n    = b / 6;
    const int chnk = b % 6;
    const int wid  = threadIdx.x >> 5;
    const int lane = threadIdx.x & 31;

    const int k0 = chnk * 256 + wid * 32;
    const float4* base = reinterpret_cast<const float4*>(
        CG + ((size_t)n * KDIM + k0) * DDIM);

    __shared__ int s_ready;
    if (threadIdx.x == 0) s_ready = ((volatile int*)g_flag)[n];
    __syncthreads();

    if (!s_ready) {
        const float4* pf = reinterpret_cast<const float4*>(
            CG + ((size_t)n * KDIM + chnk * 256) * DDIM) + threadIdx.x;
        float ax = 0.f, ay = 0.f, az = 0.f, aw = 0.f;
        #pragma unroll 8
        for (int i = 0; i < 32; i++) {
            float4 v = __ldcg(pf + i * 256);
            ax += v.x; ay += v.y; az += v.z; aw += v.w;
        }
        if (__float_as_uint((ax + ay) + (az + aw)) == 0xDEADBEEFu)
            g_dummy = ax;
        if (threadIdx.x == 0) {
            while (((volatile int*)g_flag)[n] == 0) __nanosleep(128);
            __threadfence();
        }
    }
    __syncthreads();

    const float4 gv = reinterpret_cast<const float4*>(g_G + (size_t)n * DDIM)[lane];
    float* outp = g_partial + (size_t)k0 * NATOMS + n;

    #pragma unroll
    for (int it = 0; it < 8; it++) {
        const float4* p = base + (size_t)(it * 4) * 32 + lane;
        float4 v0 = __ldcs(p + 0 * 32);
        float4 v1 = __ldcs(p + 1 * 32);
        float4 v2 = __ldcs(p + 2 * 32);
        float4 v3 = __ldcs(p + 3 * 32);
        float s0 = v0.x * gv.x + v0.y * gv.y + v0.z * gv.z + v0.w * gv.w;
        float s1 = v1.x * gv.x + v1.y * gv.y + v1.z * gv.z + v1.w * gv.w;
        float s2 = v2.x * gv.x + v2.y * gv.y + v2.z * gv.z + v2.w * gv.w;
        float s3 = v3.x * gv.x + v3.y * gv.y + v3.z * gv.z + v3.w * gv.w;
        #pragma unroll
        for (int off = 16; off > 0; off >>= 1) {
            s0 += __shfl_xor_sync(0xFFFFFFFFu, s0, off);
            s1 += __shfl_xor_sync(0xFFFFFFFFu, s1, off);
            s2 += __shfl_xor_sync(0xFFFFFFFFu, s2, off);
            s3 += __shfl_xor_sync(0xFFFFFFFFu, s3, off);
        }
        if (lane == 0) {
            outp[(size_t)(it * 4 + 0) * NATOMS] = s0;
            outp[(size_t)(it * 4 + 1) * NATOMS] = s1;
            outp[(size_t)(it * 4 + 2) * NATOMS] = s2;
            outp[(size_t)(it * 4 + 3) * NATOMS] = s3;
        }
    }
}

// ---------------------------------------------------------------------------
// Kernel 3: deterministic reduce (PDL secondary of stream) + flag reset.
// ---------------------------------------------------------------------------
__global__ void nnp_reduce_kernel(float* __restrict__ out,
                                  const float* __restrict__ volume)
{
    asm volatile("griddepcontrol.wait;");   // stream grid's stores visible

    if (blockIdx.x == 0) {
        g_flag[threadIdx.x]       = 0;
        g_flag[threadIdx.x + 256] = 0;
    }

    const int k    = blockIdx.x * 8 + (threadIdx.x >> 5);
    const int lane = threadIdx.x & 31;
    if (k >= KTOT) return;

    const float* src = (k < KDIM) ? (g_partial + (size_t)k * NATOMS)
                                  : (g_separt + (size_t)(k - KDIM) * NATOMS);
    const float4* base = reinterpret_cast<const float4*>(src);
    float4 v0 = base[lane + 0 * 32];
    float4 v1 = base[lane + 1 * 32];
    float4 v2 = base[lane + 2 * 32];
    float4 v3 = base[lane + 3 * 32];
    float s = (v0.x + v0.y + v0.z + v0.w) + (v1.x + v1.y + v1.z + v1.w)
            + (v2.x + v2.y + v2.z + v2.w) + (v3.x + v3.y + v3.z + v3.w);
    #pragma unroll
    for (int off = 16; off > 0; off >>= 1)
        s += __shfl_xor_sync(0xFFFFFFFFu, s, off);

    if (lane == 0) {
        if (k < KDIM)             out[1 + k] = s;
        else if (k < KDIM + NSTR) out[1 + KDIM + (k - KDIM)] = -s / volume[0];
        else                      out[0] = s;
    }
}

extern "C" void kernel_launch(void* const* d_in, const int* in_sizes, int n_in,
                              void* d_out, int out_size)
{
    const float* desc    = (const float*)d_in[0];
    const float* CG      = (const float*)d_in[1];
    const float* SG      = (const float*)d_in[2];
    const float* W0      = (const float*)d_in[3];
    const float* b0      = (const float*)d_in[4];
    const float* W1      = (const float*)d_in[5];
    const float* b1      = (const float*)d_in[6];
    const float* W2      = (const float*)d_in[7];
    const float* b2      = (const float*)d_in[8];
    const float* volume  = (const float*)d_in[9];
    const int*   species = (const int*)  d_in[10];
    float* out = (float*)d_out;

    const int mlp_smem = (2 * DDIM * WS + 4 * TILE * XS + 2 * MLP_THREADS) * sizeof(float);
    cudaFuncSetAttribute(nnp_mlp_kernel,
                         cudaFuncAttributeMaxDynamicSharedMemorySize, mlp_smem);

    nnp_mlp_kernel<<<NTILES_MAX, MLP_THREADS, mlp_smem>>>(
        desc, SG, W0, b0, W1, b1, W2, b2, species);

    cudaLaunchAttribute pdl[1];
    pdl[0].id = cudaLaunchAttributeProgrammaticStreamSerialization;
    pdl[0].val.programmaticStreamSerializationAllowed = 1;

    cudaLaunchConfig_t cfg = {};
    cfg.gridDim  = dim3(NATOMS * 6);
    cfg.blockDim = dim3(256);
    cfg.dynamicSmemBytes = 0;
    cfg.stream = 0;
    cfg.attrs = pdl;
    cfg.numAttrs = 1;
    cudaLaunchKernelEx(&cfg, nnp_stream_kernel, CG);

    cudaLaunchConfig_t cfg2 = {};
    cfg2.gridDim  = dim3((KTOT + 7) / 8);
    cfg2.blockDim = dim3(256);
    cfg2.dynamicSmemBytes = 0;
    cfg2.stream = 0;
    cfg2.attrs = pdl;
    cfg2.numAttrs = 1;
    cudaLaunchKernelEx(&cfg2, nnp_reduce_kernel, out, volume);
}